// round 13
// baseline (speedup 1.0000x reference)
#include <cuda_runtime.h>
#include <cuda_bf16.h>

#define N_COLS 2048                 // hidden dim
#define VECS_PER_ROW (N_COLS / 4)   // 512 float4
#define THREADS 256                 // 2 float4 per thread
#define NWARPS (THREADS / 32)
#define EPS 1e-5f

// FINAL (R7 structure, best measured: 35.94us kernel, 7.46 TB/s effective =
// 93% of the 8 TB/s HBM spec). RMSNorm over [16384, 2048] fp32 is bound by
// HBM mixed read/write turnaround. Plateau verified across occ 27-89%,
// MLP 2-16, CTA 128-256, persistent/pipelined variants, and all load/store
// cache policies (__ldcs/__ldcg/__stcs/__stwt). Winning ingredients, each
// verified in isolation:
//  - row-per-CTA, 256 threads (best occupancy quantization at 32 regs)
//  - 2x LDG.128 via __ldcg (zero-reuse stream; skip L1 fill)
//  - shuffle-tree warp reduce + SINGLE-barrier smem block reduce
//    (the only change that ever beat the noise floor)
//  - default-policy stores and g loads
// NB: redux.sync.add.f32 is NOT supported on sm_103 (ptxas rejects).

__global__ __launch_bounds__(THREADS)
void rmsnorm_kernel(const float4* __restrict__ x,
                    const float4* __restrict__ g,
                    float4* __restrict__ out)
{
    const int row = blockIdx.x;
    const float4* xr = x + (size_t)row * VECS_PER_ROW;
    float4* outr = out + (size_t)row * VECS_PER_ROW;

    const int t = threadIdx.x;
    const int warp = t >> 5;
    const int lane = t & 31;

    // x has zero reuse within a launch: bypass L1 fill (L2-only).
    float4 v0 = __ldcg(&xr[t]);
    float4 v1 = __ldcg(&xr[t + THREADS]);

    float ss = v0.x * v0.x + v0.y * v0.y + v0.z * v0.z + v0.w * v0.w
             + v1.x * v1.x + v1.y * v1.y + v1.z * v1.z + v1.w * v1.w;

    // Warp reduce.
    #pragma unroll
    for (int off = 16; off > 0; off >>= 1)
        ss += __shfl_xor_sync(0xFFFFFFFFu, ss, off);

    // Single-barrier block reduce: publish 8 warp partials, then every
    // thread sums all 8 from smem (broadcast reads, no second barrier,
    // no serialized warp0 chain).
    __shared__ float warp_sums[NWARPS];
    if (lane == 0) warp_sums[warp] = ss;
    __syncthreads();

    float total = 0.0f;
    #pragma unroll
    for (int w = 0; w < NWARPS; w++)
        total += warp_sums[w];

    const float scale = rsqrtf(total * (1.0f / (float)N_COLS) + EPS);

    // g: 8 KB, broadcast across all rows — default policy, L1/L2-resident.
    float4 g0 = g[t];
    float4 g1 = g[t + THREADS];

    float4 o0, o1;
    o0.x = v0.x * scale * g0.x;
    o0.y = v0.y * scale * g0.y;
    o0.z = v0.z * scale * g0.z;
    o0.w = v0.w * scale * g0.w;
    o1.x = v1.x * scale * g1.x;
    o1.y = v1.y * scale * g1.y;
    o1.z = v1.z * scale * g1.z;
    o1.w = v1.w * scale * g1.w;

    outr[t] = o0;
    outr[t + THREADS] = o1;
}

extern "C" void kernel_launch(void* const* d_in, const int* in_sizes, int n_in,
                              void* d_out, int out_size)
{
    const float4* x = (const float4*)d_in[0];
    const float4* g = (const float4*)d_in[1];
    float4* out = (float4*)d_out;

    const int n_rows = in_sizes[0] / N_COLS;  // 16384

    rmsnorm_kernel<<<n_rows, THREADS>>>(x, g, out);
}

// round 14
// speedup vs baseline: 1.0153x; 1.0153x over previous
#include <cuda_runtime.h>
#include <cuda_bf16.h>

#define N_COLS 2048                 // hidden dim
#define VECS_PER_ROW (N_COLS / 4)   // 512 float4
#define THREADS 256                 // 2 float4 per thread
#define NWARPS (THREADS / 32)
#define EPS 1e-5f

// Final matrix cell: single-barrier block reduce (R7's verified win) with
// DEFAULT-policy x loads (deconfounding __ldcg, which was added in the same
// round as the reduce change). RMSNorm [16384,2048] fp32 is HBM-bound at
// ~7.4 TB/s effective (93% of spec); noise floor ±0.4us kernel.

__global__ __launch_bounds__(THREADS)
void rmsnorm_kernel(const float4* __restrict__ x,
                    const float4* __restrict__ g,
                    float4* __restrict__ out)
{
    const int row = blockIdx.x;
    const float4* xr = x + (size_t)row * VECS_PER_ROW;
    float4* outr = out + (size_t)row * VECS_PER_ROW;

    const int t = threadIdx.x;
    const int warp = t >> 5;
    const int lane = t & 31;

    // Default-policy loads (the only delta vs the R7 best kernel).
    float4 v0 = xr[t];
    float4 v1 = xr[t + THREADS];

    float ss = v0.x * v0.x + v0.y * v0.y + v0.z * v0.z + v0.w * v0.w
             + v1.x * v1.x + v1.y * v1.y + v1.z * v1.z + v1.w * v1.w;

    // Warp reduce (redux.sync.add.f32 is NOT supported on sm_103).
    #pragma unroll
    for (int off = 16; off > 0; off >>= 1)
        ss += __shfl_xor_sync(0xFFFFFFFFu, ss, off);

    // Single-barrier block reduce: publish 8 warp partials, then every
    // thread sums all 8 from smem (broadcast reads, no second barrier,
    // no serialized warp0 chain).
    __shared__ float warp_sums[NWARPS];
    if (lane == 0) warp_sums[warp] = ss;
    __syncthreads();

    float total = 0.0f;
    #pragma unroll
    for (int w = 0; w < NWARPS; w++)
        total += warp_sums[w];

    const float scale = rsqrtf(total * (1.0f / (float)N_COLS) + EPS);

    // g: 8 KB, broadcast across all rows — default policy, L1/L2-resident.
    float4 g0 = g[t];
    float4 g1 = g[t + THREADS];

    float4 o0, o1;
    o0.x = v0.x * scale * g0.x;
    o0.y = v0.y * scale * g0.y;
    o0.z = v0.z * scale * g0.z;
    o0.w = v0.w * scale * g0.w;
    o1.x = v1.x * scale * g1.x;
    o1.y = v1.y * scale * g1.y;
    o1.z = v1.z * scale * g1.z;
    o1.w = v1.w * scale * g1.w;

    outr[t] = o0;
    outr[t + THREADS] = o1;
}

extern "C" void kernel_launch(void* const* d_in, const int* in_sizes, int n_in,
                              void* d_out, int out_size)
{
    const float4* x = (const float4*)d_in[0];
    const float4* g = (const float4*)d_in[1];
    float4* out = (float4*)d_out;

    const int n_rows = in_sizes[0] / N_COLS;  // 16384

    rmsnorm_kernel<<<n_rows, THREADS>>>(x, g, out);
}

// round 15
// speedup vs baseline: 1.0190x; 1.0037x over previous
#include <cuda_runtime.h>
#include <cuda_bf16.h>

#define N_COLS 2048                 // hidden dim
#define VECS_PER_ROW (N_COLS / 4)   // 512 float4
#define THREADS 256                 // 2 float4 per thread
#define NWARPS (THREADS / 32)
#define EPS 1e-5f

// FINAL — best measured configuration across 14 rounds (R7: 35.94us kernel,
// 43.49us wall, 7.46 TB/s effective = 93% of the 8 TB/s HBM spec).
//
// RMSNorm over [16384, 2048] fp32 moves a mandatory 128 MB read + 128 MB
// write per launch and is bound by HBM mixed read/write turnaround.
// Exhaustively verified plateau (35.9-37.1us) across:
//   occupancy 27-89%, per-thread MLP 2-16, CTA 128/256, warp-per-row,
//   persistent + double-buffered pipelining, named barriers,
//   __ldcs/__ldcg/default loads, __stcs/__stwt/default stores.
// Run-to-run noise on identical source: +/-0.4us kernel, +/-0.6us wall.
//
// Notes for future sessions:
//   - redux.sync.add.f32 is NOT supported on sm_103 (ptxas rejects it).
//   - dram__cycles_active (~74%) understates real throughput here; bytes/time
//     says 93% of spec. Don't chase the percentage.
//   - L2 residency across graph replays doesn't materialize (128 MB cyclic
//     sweep through ~126 MB L2 = thrash).

__global__ __launch_bounds__(THREADS)
void rmsnorm_kernel(const float4* __restrict__ x,
                    const float4* __restrict__ g,
                    float4* __restrict__ out)
{
    const int row = blockIdx.x;
    const float4* xr = x + (size_t)row * VECS_PER_ROW;
    float4* outr = out + (size_t)row * VECS_PER_ROW;

    const int t = threadIdx.x;
    const int warp = t >> 5;
    const int lane = t & 31;

    // x has zero reuse within a launch: skip L1 fill (measured neutral vs
    // default, kept from the best-measured run).
    float4 v0 = __ldcg(&xr[t]);
    float4 v1 = __ldcg(&xr[t + THREADS]);

    float ss = v0.x * v0.x + v0.y * v0.y + v0.z * v0.z + v0.w * v0.w
             + v1.x * v1.x + v1.y * v1.y + v1.z * v1.z + v1.w * v1.w;

    // Warp reduce.
    #pragma unroll
    for (int off = 16; off > 0; off >>= 1)
        ss += __shfl_xor_sync(0xFFFFFFFFu, ss, off);

    // Single-barrier block reduce: publish 8 warp partials, then every
    // thread sums all 8 from smem (broadcast reads, no second barrier,
    // no serialized warp0 chain).
    __shared__ float warp_sums[NWARPS];
    if (lane == 0) warp_sums[warp] = ss;
    __syncthreads();

    float total = 0.0f;
    #pragma unroll
    for (int w = 0; w < NWARPS; w++)
        total += warp_sums[w];

    const float scale = rsqrtf(total * (1.0f / (float)N_COLS) + EPS);

    // g: 8 KB, broadcast across all rows — default policy, L1/L2-resident.
    float4 g0 = g[t];
    float4 g1 = g[t + THREADS];

    float4 o0, o1;
    o0.x = v0.x * scale * g0.x;
    o0.y = v0.y * scale * g0.y;
    o0.z = v0.z * scale * g0.z;
    o0.w = v0.w * scale * g0.w;
    o1.x = v1.x * scale * g1.x;
    o1.y = v1.y * scale * g1.y;
    o1.z = v1.z * scale * g1.z;
    o1.w = v1.w * scale * g1.w;

    outr[t] = o0;
    outr[t + THREADS] = o1;
}

extern "C" void kernel_launch(void* const* d_in, const int* in_sizes, int n_in,
                              void* d_out, int out_size)
{
    const float4* x = (const float4*)d_in[0];
    const float4* g = (const float4*)d_in[1];
    float4* out = (float4*)d_out;

    const int n_rows = in_sizes[0] / N_COLS;  // 16384

    rmsnorm_kernel<<<n_rows, THREADS>>>(x, g, out);
}